// round 1
// baseline (speedup 1.0000x reference)
#include <cuda_runtime.h>
#include <cuda_bf16.h>

#define B_ 64
#define T_ 4096
#define N_ 32
#define D_ 64
#define LOG2PI_F 1.837877066409345f

// Scratch for emission log-probs: B*T*N floats = 33.5 MB (fits in L2).
__device__ float g_logB[(size_t)B_ * T_ * N_];

// ---------------------------------------------------------------------------
// Kernel 1: emissions. logB[b,t,n] = -0.5*(sum_d x*(x*iv - 2*mu*iv) + K_n)
// K_n = sum_d (mu^2*iv + log_var) + D*log(2pi)
// Block: 256 threads = 32 n-lanes x 8 slots, each slot handles 4 t's.
// Grid: (T/32, B).
// ---------------------------------------------------------------------------
__global__ void __launch_bounds__(256) emission_kernel(
    const float* __restrict__ X,
    const float* __restrict__ mus,
    const float* __restrict__ logvars)
{
    __shared__ float4 ivs4[16 * 32];   // [d4][n] -> iv components d4*4..d4*4+3
    __shared__ float4 ws4[16 * 32];    // w = -2*mu*iv
    __shared__ float4 Xs4[32 * 16];    // [trow][d4]
    __shared__ float  Kc[32];

    const int tid = threadIdx.x;
    const int b   = blockIdx.y;
    const int t0  = blockIdx.x * 32;

    float* ivs = reinterpret_cast<float*>(ivs4);
    float* ws  = reinterpret_cast<float*>(ws4);

    // Per-state params -> shared (layout: ((d>>2)*32 + n)*4 + (d&3))
    for (int idx = tid; idx < N_ * D_; idx += 256) {
        int n = idx >> 6;          // idx / D_
        int d = idx & 63;
        float lv = logvars[idx];
        float iv = __expf(-lv);
        int off = ((d >> 2) * 32 + n) * 4 + (d & 3);
        ivs[off] = iv;
        ws[off]  = -2.0f * mus[idx] * iv;
    }
    // X tile: 32 rows x 64 floats, contiguous
    const float4* Xv = reinterpret_cast<const float4*>(X + ((size_t)b * T_ + t0) * D_);
    for (int idx = tid; idx < 32 * 16; idx += 256) Xs4[idx] = Xv[idx];
    __syncthreads();

    if (tid < N_) {
        float k = D_ * LOG2PI_F;
        #pragma unroll 8
        for (int d = 0; d < D_; ++d) {
            float mu = mus[tid * D_ + d];
            float iv = ivs[((d >> 2) * 32 + tid) * 4 + (d & 3)];
            k += mu * mu * iv + logvars[tid * D_ + d];
        }
        Kc[tid] = k;
    }
    __syncthreads();

    const int n    = tid & 31;
    const int slot = tid >> 5;
    const int tb   = slot * 4;   // local t base (4 rows per thread)

    float acc0 = 0.f, acc1 = 0.f, acc2 = 0.f, acc3 = 0.f;
    #pragma unroll
    for (int d4 = 0; d4 < 16; ++d4) {
        float4 iv = ivs4[d4 * 32 + n];
        float4 w  = ws4[d4 * 32 + n];
        float4 x0 = Xs4[(tb + 0) * 16 + d4];
        float4 x1 = Xs4[(tb + 1) * 16 + d4];
        float4 x2 = Xs4[(tb + 2) * 16 + d4];
        float4 x3 = Xs4[(tb + 3) * 16 + d4];
        acc0 = fmaf(x0.x, fmaf(x0.x, iv.x, w.x), acc0);
        acc0 = fmaf(x0.y, fmaf(x0.y, iv.y, w.y), acc0);
        acc0 = fmaf(x0.z, fmaf(x0.z, iv.z, w.z), acc0);
        acc0 = fmaf(x0.w, fmaf(x0.w, iv.w, w.w), acc0);
        acc1 = fmaf(x1.x, fmaf(x1.x, iv.x, w.x), acc1);
        acc1 = fmaf(x1.y, fmaf(x1.y, iv.y, w.y), acc1);
        acc1 = fmaf(x1.z, fmaf(x1.z, iv.z, w.z), acc1);
        acc1 = fmaf(x1.w, fmaf(x1.w, iv.w, w.w), acc1);
        acc2 = fmaf(x2.x, fmaf(x2.x, iv.x, w.x), acc2);
        acc2 = fmaf(x2.y, fmaf(x2.y, iv.y, w.y), acc2);
        acc2 = fmaf(x2.z, fmaf(x2.z, iv.z, w.z), acc2);
        acc2 = fmaf(x2.w, fmaf(x2.w, iv.w, w.w), acc2);
        acc3 = fmaf(x3.x, fmaf(x3.x, iv.x, w.x), acc3);
        acc3 = fmaf(x3.y, fmaf(x3.y, iv.y, w.y), acc3);
        acc3 = fmaf(x3.z, fmaf(x3.z, iv.z, w.z), acc3);
        acc3 = fmaf(x3.w, fmaf(x3.w, iv.w, w.w), acc3);
    }
    float k = Kc[n];
    float* outp = g_logB + ((size_t)b * T_ + t0 + tb) * N_ + n;
    outp[0 * N_] = -0.5f * (acc0 + k);
    outp[1 * N_] = -0.5f * (acc1 + k);
    outp[2 * N_] = -0.5f * (acc2 + k);
    outp[3 * N_] = -0.5f * (acc3 + k);
}

// ---------------------------------------------------------------------------
// Kernel 2: scaled forward recursion. One warp per batch element.
// Lane j owns state j. A columns register-resident. Lag-2 renormalization so
// the warp-sum + rcp are off the loop-carried critical path.
// ---------------------------------------------------------------------------
__device__ __forceinline__ float wmax(float v) {
    #pragma unroll
    for (int o = 16; o; o >>= 1) v = fmaxf(v, __shfl_xor_sync(0xffffffffu, v, o));
    return v;
}
__device__ __forceinline__ float wsum(float v) {
    #pragma unroll
    for (int o = 16; o; o >>= 1) v += __shfl_xor_sync(0xffffffffu, v, o);
    return v;
}

__global__ void __launch_bounds__(32, 1) forward_kernel(
    const float* __restrict__ Tm,
    const float* __restrict__ priors,
    const float* __restrict__ lB,
    float* __restrict__ out)
{
    const int b = blockIdx.x;
    const int j = threadIdx.x;
    const unsigned FULL = 0xffffffffu;

    // A[i][j] = softmax(row i)[j], column j in registers
    float Acol[N_];
    #pragma unroll
    for (int i = 0; i < N_; ++i) {
        float raw = Tm[i * N_ + j];
        float mx  = wmax(raw);
        float e   = __expf(raw - mx);
        float s   = wsum(e);
        Acol[i]   = e * __frcp_rn(s);
    }

    // log pi
    float p  = priors[j];
    float pm = wmax(p);
    float pe = __expf(p - pm);
    float ps = wsum(pe);
    float lpi = (p - pm) - __logf(ps);

    const float* lbp = lB + (size_t)b * T_ * N_ + j;
    float* outb = out + (size_t)b * T_;

    // t = 0
    float a0  = lpi + lbp[0];
    float m0  = wmax(a0);
    float u   = __expf(a0 - m0);
    float sig = wsum(u);
    float ls0 = __logf(sig);
    double S  = (double)m0;                // true = u * exp(S)
    if (j == 0) outb[0] = (float)(S + (double)ls0);

    // Scale pipeline (lag-2): r_use applied this step, r_pend next rotate.
    float r_use = __frcp_rn(sig), r_pend = r_use;
    float l_use = ls0,            l_pend = ls0;

    // Emission transform pipeline: (m,e) ready for t and t+1; raw lb queue t+2,t+3.
    float lb1 = lbp[(size_t)1 * N_];
    float lb2 = lbp[(size_t)2 * N_];
    float m_cur = wmax(lb1);
    float e_cur = __expf(lb1 - m_cur);
    float m_nxt = wmax(lb2);
    float e_nxt = __expf(lb2 - m_nxt);
    float q0 = lbp[(size_t)3 * N_];
    float q1 = (4 < T_) ? lbp[(size_t)4 * N_] : 0.f;
    float er_cur = e_cur * r_use;          // emission * applied scale for t=1

    for (int t = 1; t < T_; ++t) {
        // prefetch raw logB for t+4
        float lb_new = (t + 4 < T_) ? lbp[(size_t)(t + 4) * N_] : 0.f;
        // emission transform for t+2 (latency-tolerant: used 2 iters later)
        float m2 = wmax(q0);
        float e2 = __expf(q0 - m2);

        // ---- loop-carried critical path: matvec tmp[j] = sum_i u[i]*A[i][j]
        float ac0 = 0.f, ac1 = 0.f, ac2 = 0.f, ac3 = 0.f;
        #pragma unroll
        for (int i = 0; i < N_; i += 4) {
            ac0 = fmaf(__shfl_sync(FULL, u, i + 0), Acol[i + 0], ac0);
            ac1 = fmaf(__shfl_sync(FULL, u, i + 1), Acol[i + 1], ac1);
            ac2 = fmaf(__shfl_sync(FULL, u, i + 2), Acol[i + 2], ac2);
            ac3 = fmaf(__shfl_sync(FULL, u, i + 3), Acol[i + 3], ac3);
        }
        float tmp = (ac0 + ac1) + (ac2 + ac3);
        float un  = er_cur * tmp;          // u_t (scaled by r_use, lag-2)

        // ---- bookkeeping (off critical path)
        S += (double)(m_cur) + (double)(l_use);   // S_t = S_{t-1} + m_t + log(1/rho_t)
        float sn = wsum(un);
        float lc = __logf(sn);
        if (j == 0) outb[t] = (float)(S + (double)lc);

        // rotate scale pipeline (lag-2)
        r_use = r_pend; l_use = l_pend;
        r_pend = __frcp_rn(sn); l_pend = lc;

        // rotate emission pipeline
        er_cur = e_nxt * r_use;
        m_cur = m_nxt;
        m_nxt = m2; e_nxt = e2;
        q0 = q1; q1 = lb_new;

        u = un;
    }
}

extern "C" void kernel_launch(void* const* d_in, const int* in_sizes, int n_in,
                              void* d_out, int out_size)
{
    const float* X       = (const float*)d_in[0];  // (B,T,D)
    const float* Tm      = (const float*)d_in[1];  // (N,N)
    const float* priors  = (const float*)d_in[2];  // (N,)
    const float* mus     = (const float*)d_in[3];  // (N,D)
    const float* logvars = (const float*)d_in[4];  // (N,D)
    float* outp          = (float*)d_out;          // (B,T)

    float* logB;
    cudaGetSymbolAddress((void**)&logB, g_logB);

    dim3 egrid(T_ / 32, B_);
    emission_kernel<<<egrid, 256>>>(X, mus, logvars);
    forward_kernel<<<B_, 32>>>(Tm, priors, logB, outp);
}

// round 2
// speedup vs baseline: 1.0218x; 1.0218x over previous
#include <cuda_runtime.h>
#include <cuda_bf16.h>

#define B_ 64
#define T_ 4096
#define N_ 32
#define D_ 64
#define LOG2PI_F 1.837877066409345f

// Scratch for emission log-probs: B*T*N floats = 33.5 MB (fits in L2).
__device__ float g_logB[(size_t)B_ * T_ * N_];

// ---------------------------------------------------------------------------
// Kernel 1: emissions. logB[b,t,n] = -0.5*(sum_d x*(x*iv - 2*mu*iv) + K_n)
// K_n = sum_d (mu^2*iv + log_var) + D*log(2pi)
// Block: 256 threads = 32 n-lanes x 8 slots, each slot handles 4 t's.
// Grid: (T/32, B).
// ---------------------------------------------------------------------------
__global__ void __launch_bounds__(256) emission_kernel(
    const float* __restrict__ X,
    const float* __restrict__ mus,
    const float* __restrict__ logvars)
{
    __shared__ float4 ivs4[16 * 32];   // [d4][n] -> iv components d4*4..d4*4+3
    __shared__ float4 ws4[16 * 32];    // w = -2*mu*iv
    __shared__ float4 Xs4[32 * 16];    // [trow][d4]
    __shared__ float  Kc[32];

    const int tid = threadIdx.x;
    const int b   = blockIdx.y;
    const int t0  = blockIdx.x * 32;

    float* ivs = reinterpret_cast<float*>(ivs4);
    float* ws  = reinterpret_cast<float*>(ws4);

    // Per-state params -> shared (layout: ((d>>2)*32 + n)*4 + (d&3))
    for (int idx = tid; idx < N_ * D_; idx += 256) {
        int n = idx >> 6;          // idx / D_
        int d = idx & 63;
        float lv = logvars[idx];
        float iv = __expf(-lv);
        int off = ((d >> 2) * 32 + n) * 4 + (d & 3);
        ivs[off] = iv;
        ws[off]  = -2.0f * mus[idx] * iv;
    }
    // X tile: 32 rows x 64 floats, contiguous
    const float4* Xv = reinterpret_cast<const float4*>(X + ((size_t)b * T_ + t0) * D_);
    for (int idx = tid; idx < 32 * 16; idx += 256) Xs4[idx] = Xv[idx];
    __syncthreads();

    if (tid < N_) {
        float k = D_ * LOG2PI_F;
        #pragma unroll 8
        for (int d = 0; d < D_; ++d) {
            float mu = mus[tid * D_ + d];
            float iv = ivs[((d >> 2) * 32 + tid) * 4 + (d & 3)];
            k += mu * mu * iv + logvars[tid * D_ + d];
        }
        Kc[tid] = k;
    }
    __syncthreads();

    const int n    = tid & 31;
    const int slot = tid >> 5;
    const int tb   = slot * 4;   // local t base (4 rows per thread)

    float acc0 = 0.f, acc1 = 0.f, acc2 = 0.f, acc3 = 0.f;
    #pragma unroll
    for (int d4 = 0; d4 < 16; ++d4) {
        float4 iv = ivs4[d4 * 32 + n];
        float4 w  = ws4[d4 * 32 + n];
        float4 x0 = Xs4[(tb + 0) * 16 + d4];
        float4 x1 = Xs4[(tb + 1) * 16 + d4];
        float4 x2 = Xs4[(tb + 2) * 16 + d4];
        float4 x3 = Xs4[(tb + 3) * 16 + d4];
        acc0 = fmaf(x0.x, fmaf(x0.x, iv.x, w.x), acc0);
        acc0 = fmaf(x0.y, fmaf(x0.y, iv.y, w.y), acc0);
        acc0 = fmaf(x0.z, fmaf(x0.z, iv.z, w.z), acc0);
        acc0 = fmaf(x0.w, fmaf(x0.w, iv.w, w.w), acc0);
        acc1 = fmaf(x1.x, fmaf(x1.x, iv.x, w.x), acc1);
        acc1 = fmaf(x1.y, fmaf(x1.y, iv.y, w.y), acc1);
        acc1 = fmaf(x1.z, fmaf(x1.z, iv.z, w.z), acc1);
        acc1 = fmaf(x1.w, fmaf(x1.w, iv.w, w.w), acc1);
        acc2 = fmaf(x2.x, fmaf(x2.x, iv.x, w.x), acc2);
        acc2 = fmaf(x2.y, fmaf(x2.y, iv.y, w.y), acc2);
        acc2 = fmaf(x2.z, fmaf(x2.z, iv.z, w.z), acc2);
        acc2 = fmaf(x2.w, fmaf(x2.w, iv.w, w.w), acc2);
        acc3 = fmaf(x3.x, fmaf(x3.x, iv.x, w.x), acc3);
        acc3 = fmaf(x3.y, fmaf(x3.y, iv.y, w.y), acc3);
        acc3 = fmaf(x3.z, fmaf(x3.z, iv.z, w.z), acc3);
        acc3 = fmaf(x3.w, fmaf(x3.w, iv.w, w.w), acc3);
    }
    float k = Kc[n];
    float* outp = g_logB + ((size_t)b * T_ + t0 + tb) * N_ + n;
    outp[0 * N_] = -0.5f * (acc0 + k);
    outp[1 * N_] = -0.5f * (acc1 + k);
    outp[2 * N_] = -0.5f * (acc2 + k);
    outp[3 * N_] = -0.5f * (acc3 + k);
}

// ---------------------------------------------------------------------------
// Kernel 2: scaled forward recursion. One warp per batch element.
// Lane j owns state j. A columns register-resident. Lag-2 renormalization so
// the warp-sum + rcp are off the loop-carried critical path.
// ---------------------------------------------------------------------------
__device__ __forceinline__ float wmax(float v) {
    #pragma unroll
    for (int o = 16; o; o >>= 1) v = fmaxf(v, __shfl_xor_sync(0xffffffffu, v, o));
    return v;
}
__device__ __forceinline__ float wsum(float v) {
    #pragma unroll
    for (int o = 16; o; o >>= 1) v += __shfl_xor_sync(0xffffffffu, v, o);
    return v;
}

__global__ void __launch_bounds__(32, 1) forward_kernel(
    const float* __restrict__ Tm,
    const float* __restrict__ priors,
    const float* __restrict__ lB,
    float* __restrict__ out)
{
    const int b = blockIdx.x;
    const int j = threadIdx.x;
    const unsigned FULL = 0xffffffffu;

    // A[i][j] = softmax(row i)[j], column j in registers
    float Acol[N_];
    #pragma unroll
    for (int i = 0; i < N_; ++i) {
        float raw = Tm[i * N_ + j];
        float mx  = wmax(raw);
        float e   = __expf(raw - mx);
        float s   = wsum(e);
        Acol[i]   = e * __frcp_rn(s);
    }

    // log pi
    float p  = priors[j];
    float pm = wmax(p);
    float pe = __expf(p - pm);
    float ps = wsum(pe);
    float lpi = (p - pm) - __logf(ps);

    const float* lbp = lB + (size_t)b * T_ * N_ + j;
    float* outb = out + (size_t)b * T_;

    // t = 0
    float a0  = lpi + lbp[0];
    float m0  = wmax(a0);
    float u   = __expf(a0 - m0);
    float sig = wsum(u);
    float ls0 = __logf(sig);
    double S  = (double)m0;                // true = u * exp(S)
    if (j == 0) outb[0] = (float)(S + (double)ls0);

    // Scale pipeline (lag-2): r_use applied this step, r_pend next rotate.
    float r_use = __frcp_rn(sig), r_pend = r_use;
    float l_use = ls0,            l_pend = ls0;

    // Emission transform pipeline: (m,e) ready for t and t+1; raw lb queue t+2,t+3.
    float lb1 = lbp[(size_t)1 * N_];
    float lb2 = lbp[(size_t)2 * N_];
    float m_cur = wmax(lb1);
    float e_cur = __expf(lb1 - m_cur);
    float m_nxt = wmax(lb2);
    float e_nxt = __expf(lb2 - m_nxt);
    float q0 = lbp[(size_t)3 * N_];
    float q1 = (4 < T_) ? lbp[(size_t)4 * N_] : 0.f;
    float er_cur = e_cur * r_use;          // emission * applied scale for t=1

    for (int t = 1; t < T_; ++t) {
        // prefetch raw logB for t+4
        float lb_new = (t + 4 < T_) ? lbp[(size_t)(t + 4) * N_] : 0.f;
        // emission transform for t+2 (latency-tolerant: used 2 iters later)
        float m2 = wmax(q0);
        float e2 = __expf(q0 - m2);

        // ---- loop-carried critical path: matvec tmp[j] = sum_i u[i]*A[i][j]
        float ac0 = 0.f, ac1 = 0.f, ac2 = 0.f, ac3 = 0.f;
        #pragma unroll
        for (int i = 0; i < N_; i += 4) {
            ac0 = fmaf(__shfl_sync(FULL, u, i + 0), Acol[i + 0], ac0);
            ac1 = fmaf(__shfl_sync(FULL, u, i + 1), Acol[i + 1], ac1);
            ac2 = fmaf(__shfl_sync(FULL, u, i + 2), Acol[i + 2], ac2);
            ac3 = fmaf(__shfl_sync(FULL, u, i + 3), Acol[i + 3], ac3);
        }
        float tmp = (ac0 + ac1) + (ac2 + ac3);
        float un  = er_cur * tmp;          // u_t (scaled by r_use, lag-2)

        // ---- bookkeeping (off critical path)
        S += (double)(m_cur) + (double)(l_use);   // S_t = S_{t-1} + m_t + log(1/rho_t)
        float sn = wsum(un);
        float lc = __logf(sn);
        if (j == 0) outb[t] = (float)(S + (double)lc);

        // rotate scale pipeline (lag-2)
        r_use = r_pend; l_use = l_pend;
        r_pend = __frcp_rn(sn); l_pend = lc;

        // rotate emission pipeline
        er_cur = e_nxt * r_use;
        m_cur = m_nxt;
        m_nxt = m2; e_nxt = e2;
        q0 = q1; q1 = lb_new;

        u = un;
    }
}

extern "C" void kernel_launch(void* const* d_in, const int* in_sizes, int n_in,
                              void* d_out, int out_size)
{
    const float* X       = (const float*)d_in[0];  // (B,T,D)
    const float* Tm      = (const float*)d_in[1];  // (N,N)
    const float* priors  = (const float*)d_in[2];  // (N,)
    const float* mus     = (const float*)d_in[3];  // (N,D)
    const float* logvars = (const float*)d_in[4];  // (N,D)
    float* outp          = (float*)d_out;          // (B,T)

    float* logB;
    cudaGetSymbolAddress((void**)&logB, g_logB);

    dim3 egrid(T_ / 32, B_);
    emission_kernel<<<egrid, 256>>>(X, mus, logvars);
    forward_kernel<<<B_, 32>>>(Tm, priors, logB, outp);
}